// round 10
// baseline (speedup 1.0000x reference)
#include <cuda_runtime.h>
#include <cuda_bf16.h>

#define CCONST 7.1998226
#define THREADS 256
#define MAXB 64

__device__ double g_sum[MAXB];           // zero at load; reset by finalize each run
__device__ unsigned int g_tile = 0;      // warp work-stealing ticket; reset by finalize
__device__ unsigned int g_done = 0;      // block completion ticket (atomicInc wraps)

// Warp-local fp64 reduce + atomic flush. No block sync involved.
__device__ __forceinline__ void warp_flush(double acc, int b, int lane) {
    #pragma unroll
    for (int off = 16; off; off >>= 1)
        acc += __shfl_down_sync(0xffffffffu, acc, off);
    if (lane == 0) atomicAdd(&g_sum[b], acc);
}

template <int NC>
__global__ __launch_bounds__(THREADS, 4)
void coulomb_wsteal(const float* __restrict__ dij,
                    const float* __restrict__ q,
                    float* __restrict__ out,
                    int Nrt, int B, unsigned int nChunks, unsigned int totalBlocks) {
    const int N    = (NC > 0) ? NC : Nrt;
    const int tid  = threadIdx.x;
    const int lane = tid & 31;
    const int n4   = N >> 2;             // float4s per row

    double acc = 0.0;
    int cur_b = -1;

    // first claim (latency exposed once)
    unsigned int nt = 0;
    if (lane == 0) nt = atomicAdd(&g_tile, 1u);
    unsigned int t = __shfl_sync(0xffffffffu, nt, 0);

    while (t < nChunks) {
        // prefetch next ticket on lane 0; consumed (shfl) only after compute
        if (lane == 0) nt = atomicAdd(&g_tile, 1u);

        const unsigned int r0 = 2u * t;                 // global row index
        const int b = (int)(r0 / (unsigned)N);

        if (b != cur_b) {                               // uniform within warp
            if (cur_b >= 0) { warp_flush(acc, cur_b, lane); acc = 0.0; }
            cur_b = b;
        }

        const float4* q4row = (const float4*)(q + (size_t)b * N);
        const float4* d0p   = (const float4*)(dij + (size_t)r0 * N);
        const float4* d1p   = (const float4*)(dij + ((size_t)r0 + 1) * N);

        float a0 = 0.f, a1 = 0.f, a2 = 0.f, a3 = 0.f;

        #pragma unroll 4
        for (int idx = lane; idx < n4; idx += 32) {
            float4 q4 = __ldg(q4row + idx);
            float4 d0 = __ldcs(d0p + idx);
            float4 d1 = __ldcs(d1p + idx);

            a0 += __fdividef(q4.x, d0.x) + __fdividef(q4.y, d0.y);
            a1 += __fdividef(q4.z, d0.z) + __fdividef(q4.w, d0.w);
            a2 += __fdividef(q4.x, d1.x) + __fdividef(q4.y, d1.y);
            a3 += __fdividef(q4.z, d1.z) + __fdividef(q4.w, d1.w);
        }

        const float s0 = a0 + a1;
        const float s1 = a2 + a3;
        // promote per row: q_i weights (fp64)
        acc += (double)__ldg(q + r0)     * (double)s0
             + (double)__ldg(q + r0 + 1) * (double)s1;

        t = __shfl_sync(0xffffffffu, nt, 0);            // broadcast prefetched ticket
    }

    if (cur_b >= 0) warp_flush(acc, cur_b, lane);

    // block completion (only sync in the kernel, after all work)
    __shared__ bool is_last;
    __syncthreads();
    if (tid == 0) {
        __threadfence();
        unsigned int ticket = atomicInc(&g_done, totalBlocks - 1);
        is_last = (ticket == totalBlocks - 1);
    }
    __syncthreads();

    if (is_last) {
        if (tid == 0) g_tile = 0;                       // reset ticket for next replay
        if (tid < B) {
            double total = atomicAdd(&g_sum[tid], 0.0); // coherent read
            out[tid] = (float)(CCONST * total);
            g_sum[tid] = 0.0;                           // reset for next replay
        }
    }
}

extern "C" void kernel_launch(void* const* d_in, const int* in_sizes, int n_in,
                              void* d_out, int out_size) {
    // Identify inputs by element count: largest = d_ij [B,N,N]; q = [B,N].
    int di = 0;
    for (int i = 1; i < n_in; i++)
        if (in_sizes[i] > in_sizes[di]) di = i;
    const float* dij = (const float*)d_in[di];

    const long long B = (out_size > 0) ? out_size : 16;
    int qi = (di == 0 && n_in > 1) ? 1 : 0;
    for (int i = 0; i < n_in; i++) {
        if (i == di) continue;
        long long nq = in_sizes[i];
        long long Nc = nq / B;
        if (Nc > 0 && B * Nc * Nc == (long long)in_sizes[di]) { qi = i; break; }
    }
    const float* q = (const float*)d_in[qi];

    const int N = (int)((long long)in_sizes[qi] / B);   // 2048

    int sm_count = 148;
    cudaDeviceGetAttribute(&sm_count, cudaDevAttrMultiProcessorCount, 0);

    const unsigned int nChunks = (unsigned int)((B * N) / 2);   // 2 rows per chunk
    unsigned int blocks = (unsigned int)(sm_count * 4);         // 4 CTAs/SM exactly
    if (blocks > nChunks / 8) blocks = nChunks / 8;

    if (N == 2048)
        coulomb_wsteal<2048><<<blocks, THREADS>>>(dij, q, (float*)d_out, N, (int)B, nChunks, blocks);
    else
        coulomb_wsteal<0><<<blocks, THREADS>>>(dij, q, (float*)d_out, N, (int)B, nChunks, blocks);
}